// round 11
// baseline (speedup 1.0000x reference)
#include <cuda_runtime.h>
#include <stdint.h>

// Problem constants
#define B_ 32
#define N_ 2048
#define M_ 16
#define K_ 32
#define H_ 2
#define NSPLIT 8
#define ROWS_PER_CHUNK (N_/NSPLIT)         // 256
#define ROWS_PER_WARP  (ROWS_PER_CHUNK/8)  // 32
#define ROW_STRIDE 20                      // smem floats per row: [w,pad,pad,pad,y0..y15]
#define TOT (B_*K_*M_)                     // 16384
#define SCHUNKS 64                         // scan chunks (16 (b,k) rows each)

// Scratch (static device globals: no allocation allowed)
__device__ float g_Tpart[NSPLIT*TOT];            // 512 KB
__device__ float g_csum_part[NSPLIT*SCHUNKS*M_]; // 32 KB

// ---------------------------------------------------------------------------
// Kernel 1: main compute. Stage only w + y (20.5 KB smem -> 3 blocks/SM,
// 24 warps/SM vs round-8's 16). zn2 = sum (y*th)^2 in-register.
// ---------------------------------------------------------------------------
__global__ void __launch_bounds__(256, 3)
main_kernel(const float* __restrict__ dgm,
            const float* __restrict__ theta,
            const float* __restrict__ cw) {
    const int b     = blockIdx.y;
    const int chunk = blockIdx.x;
    const int tid   = threadIdx.x;
    const int warp  = tid >> 5;
    const int lane  = tid & 31;          // == k

    __shared__ float pool[ROWS_PER_CHUNK * ROW_STRIDE];  // 5120 floats = 20.5 KB

    // ---- staging: 256 rows x 17 floats, coalesced; w + y only ----
    {
        const float c0 = __ldg(cw + 0);
        const float c1 = __ldg(cw + 1);
        const float* __restrict__ src =
            dgm + ((long)b * N_ + (long)chunk * ROWS_PER_CHUNK) * 17;
#pragma unroll
        for (int it = 0; it < 17; ++it) {
            const int idx = it * 256 + tid;          // 0..4351
            const int n   = idx / 17;
            const int c   = idx - n * 17;
            const float v = __ldg(src + idx);
            float* rp = pool + n * ROW_STRIDE;
            if (c == 0) {
                int h = (int)v;
                h = h < 0 ? 0 : (h > (H_ - 1) ? (H_ - 1) : h);
                rp[0] = (h == 0) ? c0 : c1;
            } else {
                rp[3 + c] = v;         // y at [4..19]
            }
        }
    }

    // theta row for this lane's k (used for zn2 AND the epilogue fold)
    float th[M_];
#pragma unroll
    for (int i = 0; i < 4; ++i) {
        float4 t = reinterpret_cast<const float4*>(theta)[lane * 4 + i];
        th[4*i+0] = t.x; th[4*i+1] = t.y; th[4*i+2] = t.z; th[4*i+3] = t.w;
    }

    float acc[M_];
#pragma unroll
    for (int m = 0; m < M_; ++m) acc[m] = 0.0f;

    __syncthreads();

    // ---- compute: warp owns rows [warp*32, warp*32+32) ----
    const float* __restrict__ rbase = pool + warp * ROWS_PER_WARP * ROW_STRIDE;
    for (int r = 0; r < ROWS_PER_WARP; ++r) {
        const float* rp = rbase + r * ROW_STRIDE;
        const float w = rp[0];
        const float4 y0 = *reinterpret_cast<const float4*>(rp + 4);
        const float4 y1 = *reinterpret_cast<const float4*>(rp + 8);
        const float4 y2v= *reinterpret_cast<const float4*>(rp + 12);
        const float4 y3 = *reinterpret_cast<const float4*>(rp + 16);

        // zn2 = sum_m (y_m*th_m)^2  (4 independent chains)
        float z;
        z = y0.x * th[0];   float d0 = z * z;
        z = y0.y * th[1];   d0 = fmaf(z, z, d0);
        z = y0.z * th[2];   d0 = fmaf(z, z, d0);
        z = y0.w * th[3];   d0 = fmaf(z, z, d0);
        z = y1.x * th[4];   float d1 = z * z;
        z = y1.y * th[5];   d1 = fmaf(z, z, d1);
        z = y1.z * th[6];   d1 = fmaf(z, z, d1);
        z = y1.w * th[7];   d1 = fmaf(z, z, d1);
        z = y2v.x * th[8];  float d2 = z * z;
        z = y2v.y * th[9];  d2 = fmaf(z, z, d2);
        z = y2v.z * th[10]; d2 = fmaf(z, z, d2);
        z = y2v.w * th[11]; d2 = fmaf(z, z, d2);
        z = y3.x * th[12];  float d3 = z * z;
        z = y3.y * th[13];  d3 = fmaf(z, z, d3);
        z = y3.z * th[14];  d3 = fmaf(z, z, d3);
        z = y3.w * th[15];  d3 = fmaf(z, z, d3);
        const float u = (d0 + d1) + (d2 + d3);

        // scale = asinh(sqrt(u))/(2*sqrt(u)); small-u poly else MUFU path
        const float p   = 0.5f + u * (-0.08333333333f + u * 0.0375f);
        const float irs = rsqrtf(u);
        const float s1  = __fsqrt_rn(1.0f + u);
        const float rr  = u * irs;
        const float l   = __logf(rr + s1);
        const float sm  = 0.5f * l * irs;
        const float scale = (u < 0.0025f) ? p : sm;
        const float c = w * scale;

        acc[0]  = fmaf(c, y0.x,  acc[0]);   acc[1]  = fmaf(c, y0.y,  acc[1]);
        acc[2]  = fmaf(c, y0.z,  acc[2]);   acc[3]  = fmaf(c, y0.w,  acc[3]);
        acc[4]  = fmaf(c, y1.x,  acc[4]);   acc[5]  = fmaf(c, y1.y,  acc[5]);
        acc[6]  = fmaf(c, y1.z,  acc[6]);   acc[7]  = fmaf(c, y1.w,  acc[7]);
        acc[8]  = fmaf(c, y2v.x, acc[8]);   acc[9]  = fmaf(c, y2v.y, acc[9]);
        acc[10] = fmaf(c, y2v.z, acc[10]);  acc[11] = fmaf(c, y2v.w, acc[11]);
        acc[12] = fmaf(c, y3.x,  acc[12]);  acc[13] = fmaf(c, y3.y,  acc[13]);
        acc[14] = fmaf(c, y3.z,  acc[14]);  acc[15] = fmaf(c, y3.w,  acc[15]);
    }

    // ---- epilogue: fold theta, reduce 8 warps, write partial + chunk sums ----
    __syncthreads();                       // staging buffer now reusable
#pragma unroll
    for (int m = 0; m < M_; ++m)
        pool[(warp * K_ + lane) * 17 + m] = acc[m] * th[m];
    __syncthreads();

    float* tsum = pool + 4352;             // [K_][M_] per-(k,m) totals (512 fl)
#pragma unroll
    for (int idx = tid; idx < K_ * M_; idx += 256) {
        const int kk = idx >> 4, mm = idx & 15;
        float s = 0.0f;
#pragma unroll
        for (int w = 0; w < 8; ++w) s += pool[(w * K_ + kk) * 17 + mm];
        g_Tpart[(long)chunk * TOT + (long)b * (K_ * M_) + idx] = s;
        tsum[idx] = s;
    }
    __syncthreads();

    // per-scan-chunk partial column sums: halves h=0 (k<16), h=1 (k>=16)
    if (tid < 2 * M_) {
        const int h = tid >> 4, m = tid & 15;
        float s = 0.0f;
#pragma unroll
        for (int k = 0; k < 16; ++k) s += tsum[(h * 16 + k) * M_ + m];
        g_csum_part[(long)chunk * (SCHUNKS * M_) + (b * 2 + h) * M_ + m] = s;
    }
}

// ---------------------------------------------------------------------------
// XLA's f32 tanh approximation (rational 13/6, clamp +-9, |x|<4e-4 -> x).
// Tracks the JAX reference where 1/(1-tanh^2) amplifies ULP noise.
// ---------------------------------------------------------------------------
__device__ __forceinline__ float xla_tanhf(float x) {
    const float ax = fabsf(x);
    float xc = fminf(fmaxf(x, -9.0f), 9.0f);
    float x2 = xc * xc;
    float num = fmaf(x2, -2.76076847742355e-16f, 2.00018790482477e-13f);
    num = fmaf(x2, num, -8.60467152213735e-11f);
    num = fmaf(x2, num,  5.12229709037114e-08f);
    num = fmaf(x2, num,  1.48572235717979e-05f);
    num = fmaf(x2, num,  6.37261928875436e-04f);
    num = fmaf(x2, num,  4.89352455891786e-03f);
    num = xc * num;
    float den = fmaf(x2,  1.19825839466702e-06f, 1.18534705686654e-04f);
    den = fmaf(x2, den,   2.26843463243900e-03f);
    den = fmaf(x2, den,   4.89352518554385e-03f);
    float r = __fdiv_rn(num, den);
    return (ax < 0.0004f) ? x : r;
}

// ---------------------------------------------------------------------------
// Kernel 2: fused tail (round-8 proven). Block j (0..63) owns scan chunk j.
// ---------------------------------------------------------------------------
__global__ void __launch_bounds__(256)
tail_kernel(float* __restrict__ out) {
    const int j   = blockIdx.x;
    const int tid = threadIdx.x;

    __shared__ float red[256];            // reduced T for own 16 rows
    __shared__ float csum[SCHUNKS * M_];  // chunk sums (all 64 chunks)

    // (a) reduce own rows over NSPLIT
    {
        float v = 0.0f;
#pragma unroll
        for (int sp = 0; sp < NSPLIT; ++sp)
            v += g_Tpart[(long)sp * TOT + j * 256 + tid];
        red[tid] = v;
    }

    // (b) stage chunk-sum table, reduced over splits (coalesced)
#pragma unroll
    for (int idx = tid; idx < SCHUNKS * M_; idx += 256) {
        float s = 0.0f;
#pragma unroll
        for (int sp = 0; sp < NSPLIT; ++sp)
            s += g_csum_part[(long)sp * (SCHUNKS * M_) + idx];
        csum[idx] = s;
    }
    __syncthreads();

    // (c) prefixes + exp map
    const int ri = tid >> 4;   // row within chunk, 0..15
    const int m  = tid & 15;

    float pref = 0.0f;
    for (int j2 = 0; j2 < j; ++j2) pref += csum[j2 * M_ + m];

    float intra = 0.0f;
#pragma unroll
    for (int i = 0; i < M_; ++i) if (i <= ri) intra += red[i * M_ + m];

    const float S = pref + intra;

    float tot = __fmul_rn(S, S);
#pragma unroll
    for (int d = 1; d < 16; d <<= 1)
        tot = __fadd_rn(tot, __shfl_xor_sync(0xFFFFFFFFu, tot, d));

    const float sn    = __fsqrt_rn(tot);
    const float t     = xla_tanhf(sn);
    const float denom = fmaxf(sn, 1e-7f);
    const float xd    = __fdiv_rn(__fmul_rn(t, S), denom);

    float q = __fmul_rn(xd, xd);
#pragma unroll
    for (int d = 1; d < 16; d <<= 1)
        q = __fadd_rn(q, __shfl_xor_sync(0xFFFFFFFFu, q, d));

    const float omq = __fadd_rn(1.0f, -q);
    out[j * 256 + tid] = __fdiv_rn(__fmul_rn(2.0f, xd), omq);
}

// ---------------------------------------------------------------------------
extern "C" void kernel_launch(void* const* d_in, const int* in_sizes, int n_in,
                              void* d_out, int out_size) {
    const float* dgm   = nullptr;
    const float* theta = nullptr;
    const float* cw    = nullptr;
    for (int i = 0; i < n_in; ++i) {
        if      (in_sizes[i] == B_ * N_ * 17) dgm   = (const float*)d_in[i];
        else if (in_sizes[i] == K_ * M_)      theta = (const float*)d_in[i];
        else if (in_sizes[i] == H_)           cw    = (const float*)d_in[i];
    }
    main_kernel<<<dim3(NSPLIT, B_), 256>>>(dgm, theta, cw);
    tail_kernel<<<SCHUNKS, 256>>>((float*)d_out);
}

// round 12
// speedup vs baseline: 1.0206x; 1.0206x over previous
#include <cuda_runtime.h>
#include <stdint.h>

// Problem constants
#define B_ 32
#define N_ 2048
#define M_ 16
#define K_ 32
#define H_ 2
#define NSPLIT 8
#define ROWS_PER_CHUNK (N_/NSPLIT)         // 256
#define ROWS_PER_WARP  (ROWS_PER_CHUNK/8)  // 32
#define ROW_STRIDE 36                      // smem floats per row (w,pad, y[16], y2[16])
#define TOT (B_*K_*M_)                     // 16384
#define SCHUNKS 64                         // scan chunks (16 (b,k) rows each)

// Scratch (static device globals: no allocation allowed)
__device__ float g_Tpart[NSPLIT*TOT];            // 512 KB
__device__ float g_csum_part[NSPLIT*SCHUNKS*M_]; // 32 KB

// ---------------------------------------------------------------------------
// Kernel 1: main compute. Round-10 hot loop (minimal issue slots: 9 LDS +
// 16 FMA zn2 + 16 FMA acc) at 3 blocks/SM (108 KB smem, 85-reg cap).
// ---------------------------------------------------------------------------
__global__ void __launch_bounds__(256, 3)
main_kernel(const float* __restrict__ dgm,
            const float* __restrict__ theta,
            const float* __restrict__ cw) {
    const int b     = blockIdx.y;
    const int chunk = blockIdx.x;
    const int tid   = threadIdx.x;
    const int warp  = tid >> 5;
    const int lane  = tid & 31;          // == k

    __shared__ float pool[ROWS_PER_CHUNK * ROW_STRIDE];  // 36 KB

    // ---- staging: 256 rows x 17 floats, coalesced; compute w and y^2 ----
    {
        const float c0 = __ldg(cw + 0);
        const float c1 = __ldg(cw + 1);
        const float* __restrict__ src =
            dgm + ((long)b * N_ + (long)chunk * ROWS_PER_CHUNK) * 17;
#pragma unroll
        for (int it = 0; it < 17; ++it) {
            const int idx = it * 256 + tid;          // 0..4351
            const int n   = idx / 17;
            const int c   = idx - n * 17;
            const float v = __ldg(src + idx);
            float* rp = pool + n * ROW_STRIDE;
            if (c == 0) {
                int h = (int)v;
                h = h < 0 ? 0 : (h > (H_ - 1) ? (H_ - 1) : h);
                rp[0] = (h == 0) ? c0 : c1;
            } else {
                rp[3 + c]  = v;        // y  at [4..19]
                rp[19 + c] = v * v;    // y2 at [20..35]
            }
        }
    }

    // th2 for this lane's k
    float th2[M_];
#pragma unroll
    for (int i = 0; i < 4; ++i) {
        float4 t = reinterpret_cast<const float4*>(theta)[lane * 4 + i];
        th2[4*i+0] = t.x * t.x; th2[4*i+1] = t.y * t.y;
        th2[4*i+2] = t.z * t.z; th2[4*i+3] = t.w * t.w;
    }

    float acc[M_];
#pragma unroll
    for (int m = 0; m < M_; ++m) acc[m] = 0.0f;

    __syncthreads();

    // ---- compute: warp owns rows [warp*32, warp*32+32) ----
    const float* __restrict__ rbase = pool + warp * ROWS_PER_WARP * ROW_STRIDE;
    for (int r = 0; r < ROWS_PER_WARP; ++r) {
        const float* rp = rbase + r * ROW_STRIDE;
        const float w = rp[0];
        const float4 q0 = *reinterpret_cast<const float4*>(rp + 20);
        const float4 q1 = *reinterpret_cast<const float4*>(rp + 24);
        const float4 q2 = *reinterpret_cast<const float4*>(rp + 28);
        const float4 q3 = *reinterpret_cast<const float4*>(rp + 32);

        float d0 = fmaf(q0.x, th2[0],  fmaf(q0.y, th2[1],  fmaf(q0.z, th2[2],  q0.w*th2[3])));
        float d1 = fmaf(q1.x, th2[4],  fmaf(q1.y, th2[5],  fmaf(q1.z, th2[6],  q1.w*th2[7])));
        float d2 = fmaf(q2.x, th2[8],  fmaf(q2.y, th2[9],  fmaf(q2.z, th2[10], q2.w*th2[11])));
        float d3 = fmaf(q3.x, th2[12], fmaf(q3.y, th2[13], fmaf(q3.z, th2[14], q3.w*th2[15])));
        const float u = (d0 + d1) + (d2 + d3);

        // scale = asinh(sqrt(u))/(2*sqrt(u)); small-u poly else MUFU path
        const float p   = 0.5f + u * (-0.08333333333f + u * 0.0375f);
        const float irs = rsqrtf(u);
        const float s1  = __fsqrt_rn(1.0f + u);
        const float rr  = u * irs;
        const float l   = __logf(rr + s1);
        const float sm  = 0.5f * l * irs;
        const float scale = (u < 0.0025f) ? p : sm;
        const float c = w * scale;

        const float4 y0 = *reinterpret_cast<const float4*>(rp + 4);
        const float4 y1 = *reinterpret_cast<const float4*>(rp + 8);
        const float4 y2v= *reinterpret_cast<const float4*>(rp + 12);
        const float4 y3 = *reinterpret_cast<const float4*>(rp + 16);
        acc[0]  = fmaf(c, y0.x,  acc[0]);   acc[1]  = fmaf(c, y0.y,  acc[1]);
        acc[2]  = fmaf(c, y0.z,  acc[2]);   acc[3]  = fmaf(c, y0.w,  acc[3]);
        acc[4]  = fmaf(c, y1.x,  acc[4]);   acc[5]  = fmaf(c, y1.y,  acc[5]);
        acc[6]  = fmaf(c, y1.z,  acc[6]);   acc[7]  = fmaf(c, y1.w,  acc[7]);
        acc[8]  = fmaf(c, y2v.x, acc[8]);   acc[9]  = fmaf(c, y2v.y, acc[9]);
        acc[10] = fmaf(c, y2v.z, acc[10]);  acc[11] = fmaf(c, y2v.w, acc[11]);
        acc[12] = fmaf(c, y3.x,  acc[12]);  acc[13] = fmaf(c, y3.y,  acc[13]);
        acc[14] = fmaf(c, y3.z,  acc[14]);  acc[15] = fmaf(c, y3.w,  acc[15]);
    }

    // ---- epilogue: fold theta, reduce 8 warps, write partial + chunk sums ----
    __syncthreads();                       // staging buffer now reusable
    {
        float th[M_];
#pragma unroll
        for (int i = 0; i < 4; ++i) {
            float4 t = reinterpret_cast<const float4*>(theta)[lane * 4 + i];
            th[4*i+0] = t.x; th[4*i+1] = t.y; th[4*i+2] = t.z; th[4*i+3] = t.w;
        }
#pragma unroll
        for (int m = 0; m < M_; ++m)
            pool[(warp * K_ + lane) * 17 + m] = acc[m] * th[m];
    }
    __syncthreads();

    float* tsum = pool + 8192;             // [K_][M_] per-(k,m) totals
#pragma unroll
    for (int idx = tid; idx < K_ * M_; idx += 256) {
        const int kk = idx >> 4, mm = idx & 15;
        float s = 0.0f;
#pragma unroll
        for (int w = 0; w < 8; ++w) s += pool[(w * K_ + kk) * 17 + mm];
        g_Tpart[(long)chunk * TOT + (long)b * (K_ * M_) + idx] = s;
        tsum[idx] = s;
    }
    __syncthreads();

    // per-scan-chunk partial column sums: halves h=0 (k<16), h=1 (k>=16)
    if (tid < 2 * M_) {
        const int h = tid >> 4, m = tid & 15;
        float s = 0.0f;
#pragma unroll
        for (int k = 0; k < 16; ++k) s += tsum[(h * 16 + k) * M_ + m];
        g_csum_part[(long)chunk * (SCHUNKS * M_) + (b * 2 + h) * M_ + m] = s;
    }
}

// ---------------------------------------------------------------------------
// XLA's f32 tanh approximation (rational 13/6, clamp +-9, |x|<4e-4 -> x).
// Tracks the JAX reference where 1/(1-tanh^2) amplifies ULP noise.
// ---------------------------------------------------------------------------
__device__ __forceinline__ float xla_tanhf(float x) {
    const float ax = fabsf(x);
    float xc = fminf(fmaxf(x, -9.0f), 9.0f);
    float x2 = xc * xc;
    float num = fmaf(x2, -2.76076847742355e-16f, 2.00018790482477e-13f);
    num = fmaf(x2, num, -8.60467152213735e-11f);
    num = fmaf(x2, num,  5.12229709037114e-08f);
    num = fmaf(x2, num,  1.48572235717979e-05f);
    num = fmaf(x2, num,  6.37261928875436e-04f);
    num = fmaf(x2, num,  4.89352455891786e-03f);
    num = xc * num;
    float den = fmaf(x2,  1.19825839466702e-06f, 1.18534705686654e-04f);
    den = fmaf(x2, den,   2.26843463243900e-03f);
    den = fmaf(x2, den,   4.89352518554385e-03f);
    float r = __fdiv_rn(num, den);
    return (ax < 0.0004f) ? x : r;
}

// ---------------------------------------------------------------------------
// Kernel 2: fused tail. Block j owns scan chunk j. Serial 63-iter prefix loop
// replaced by strided partials + 16-lane shuffle reduction (crit path ~150cyc).
// ---------------------------------------------------------------------------
__global__ void __launch_bounds__(256)
tail_kernel(float* __restrict__ out) {
    const int j   = blockIdx.x;
    const int tid = threadIdx.x;

    __shared__ float red[256];            // reduced T for own 16 rows
    __shared__ float csum[SCHUNKS * M_];  // chunk sums (all 64 chunks)
    __shared__ float pref_s[M_];          // per-m exclusive chunk prefix

    // (a) reduce own rows over NSPLIT
    {
        float v = 0.0f;
#pragma unroll
        for (int sp = 0; sp < NSPLIT; ++sp)
            v += g_Tpart[(long)sp * TOT + j * 256 + tid];
        red[tid] = v;
    }

    // (b) stage chunk-sum table, reduced over splits (coalesced)
#pragma unroll
    for (int idx = tid; idx < SCHUNKS * M_; idx += 256) {
        float s = 0.0f;
#pragma unroll
        for (int sp = 0; sp < NSPLIT; ++sp)
            s += g_csum_part[(long)sp * (SCHUNKS * M_) + idx];
        csum[idx] = s;
    }
    __syncthreads();

    // (c) parallel chunk prefix: mapping mp=tid>>4, tp=tid&15 puts the 16
    // tp-partials of each mp inside one 16-lane shuffle group.
    {
        const int mp = tid >> 4;       // 0..15
        const int tp = tid & 15;       // 0..15
        float ps = 0.0f;
        for (int j2 = tp; j2 < j; j2 += 16) ps += csum[j2 * M_ + mp];
#pragma unroll
        for (int d = 1; d < 16; d <<= 1)
            ps += __shfl_xor_sync(0xFFFFFFFFu, ps, d);
        if (tp == 0) pref_s[mp] = ps;
    }
    __syncthreads();

    // (d) intra prefix + Poincare exp map
    const int ri = tid >> 4;   // row within chunk, 0..15
    const int m  = tid & 15;

    float intra = 0.0f;
#pragma unroll
    for (int i = 0; i < M_; ++i) if (i <= ri) intra += red[i * M_ + m];

    const float S = pref_s[m] + intra;

    float tot = __fmul_rn(S, S);
#pragma unroll
    for (int d = 1; d < 16; d <<= 1)
        tot = __fadd_rn(tot, __shfl_xor_sync(0xFFFFFFFFu, tot, d));

    const float sn    = __fsqrt_rn(tot);
    const float t     = xla_tanhf(sn);
    const float denom = fmaxf(sn, 1e-7f);
    const float xd    = __fdiv_rn(__fmul_rn(t, S), denom);

    float q = __fmul_rn(xd, xd);
#pragma unroll
    for (int d = 1; d < 16; d <<= 1)
        q = __fadd_rn(q, __shfl_xor_sync(0xFFFFFFFFu, q, d));

    const float omq = __fadd_rn(1.0f, -q);
    out[j * 256 + tid] = __fdiv_rn(__fmul_rn(2.0f, xd), omq);
}

// ---------------------------------------------------------------------------
extern "C" void kernel_launch(void* const* d_in, const int* in_sizes, int n_in,
                              void* d_out, int out_size) {
    const float* dgm   = nullptr;
    const float* theta = nullptr;
    const float* cw    = nullptr;
    for (int i = 0; i < n_in; ++i) {
        if      (in_sizes[i] == B_ * N_ * 17) dgm   = (const float*)d_in[i];
        else if (in_sizes[i] == K_ * M_)      theta = (const float*)d_in[i];
        else if (in_sizes[i] == H_)           cw    = (const float*)d_in[i];
    }
    main_kernel<<<dim3(NSPLIT, B_), 256>>>(dgm, theta, cw);
    tail_kernel<<<SCHUNKS, 256>>>((float*)d_out);
}